// round 3
// baseline (speedup 1.0000x reference)
#include <cuda_runtime.h>
#include <cstdint>

// Problem constants (ViT-B/16 @384: b=32, n=577, c=768, H=12, d=64, keep=0.7)
#define B   32
#define N   577
#define C   768
#define HH  12
#define DD  64
#define NK  576          // n-1 patch tokens
#define FT  404          // ceil(0.7*576)
#define SCALE 0.125f     // (c/H)^-0.5 = 64^-0.5

// Output layout (tuple leaves flattened, concatenated, float32):
//  x [32,577,768] | index [32,404,768] | ind [32,404] | class_attention [32,576] | final_tokens [1]
//  sizes: 14,180,352 | 9,928,704 | 12,928 | 18,432 | 1   (total 24,140,417)
#define OFF_X      0ll
#define OFF_INDEX  14180352ll
#define OFF_IND    24109056ll
#define OFF_CA     24121984ll
#define OFF_FT     24140416ll

#define FULLM 0xFFFFFFFFu

// ---------------- scratch (device globals; no allocation allowed) ------------
__device__ float g_q[B * C];               // q for CLS token, [b, h*64+d]
__device__ float g_u[B * HH * C];          // folded key-projection vectors [b,h,c]
__device__ float g_beta[B * HH];           // bias dot terms
__device__ float g_dots[B * HH * N];       // CLS attention logits
__device__ int   g_ind[B * FT];            // selected indices (sorted by construction)

// ---------------- K1: q = x[:,0,:] @ Wq + bq  (grid 32, block 768) ----------
__global__ void k_qproj(const float* __restrict__ x,
                        const float* __restrict__ W,
                        const float* __restrict__ bq) {
    int b = blockIdx.x, col = threadIdx.x;
    __shared__ float xs[C];
    xs[col] = x[(size_t)b * N * C + col];   // row 0 of batch b
    __syncthreads();
    float acc = bq[col];
#pragma unroll 4
    for (int cc = 0; cc < C; cc++)
        acc = fmaf(xs[cc], W[(size_t)cc * 3 * C + col], acc);
    g_q[b * C + col] = acc;
}

// ---------------- K2: u[b,h,c] = sum_d Wk[c,h*64+d]*q[b,h,d]; beta ----------
// grid 96 blocks (8 cc each), block 384 threads (= 32 b * 12 h)
__global__ void k_uproj(const float* __restrict__ W,
                        const float* __restrict__ bqkv) {
    int cc0 = blockIdx.x * 8;
    int tid = threadIdx.x;
    int b = tid / HH, h = tid % HH;

    float q[DD];
    const float4* qp = (const float4*)&g_q[b * C + h * DD];
#pragma unroll
    for (int i = 0; i < DD / 4; i++) {
        float4 v = qp[i];
        q[4 * i + 0] = v.x; q[4 * i + 1] = v.y; q[4 * i + 2] = v.z; q[4 * i + 3] = v.w;
    }

    __shared__ float w[C];
    for (int s = 0; s < 8; s++) {
        int cc = cc0 + s;
        __syncthreads();
        w[tid]       = W[(size_t)cc * 3 * C + C + tid];
        w[tid + 384] = W[(size_t)cc * 3 * C + C + tid + 384];
        __syncthreads();
        float acc = 0.f;
#pragma unroll
        for (int d = 0; d < DD; d++) acc = fmaf(w[h * DD + d], q[d], acc);
        g_u[(size_t)(b * HH + h) * C + cc] = acc;
    }
    if (blockIdx.x == 0) {
        float acc = 0.f;
#pragma unroll
        for (int d = 0; d < DD; d++) acc = fmaf(bqkv[C + h * DD + d], q[d], acc);
        g_beta[tid] = acc;   // tid == b*12+h
    }
}

// ---------------- K3: dots[b,h,j] = scale*(x[b,j,:]·u[b,h,:] + beta) --------
// grid (32, 16) — 37 j per block; block 256. u lives in registers (36/thread).
__global__ void __launch_bounds__(256) k_dots(const float* __restrict__ x) {
    int b = blockIdx.x, tid = threadIdx.x;
    int lane = tid & 31, warp = tid >> 5;

    float ur[HH * 3];
#pragma unroll
    for (int h = 0; h < HH; h++)
#pragma unroll
        for (int s = 0; s < 3; s++)
            ur[h * 3 + s] = g_u[(size_t)(b * HH + h) * C + s * 256 + tid];

    __shared__ float bet[HH];
    __shared__ float red[HH * 8];
    if (tid < HH) bet[tid] = g_beta[b * HH + tid];
    __syncthreads();

    int j0 = blockIdx.y * 37;
    for (int jj = 0; jj < 37; jj++) {
        int j = j0 + jj;
        if (j >= N) break;
        const float* xr = x + ((size_t)b * N + j) * C;
        float x0 = __ldg(xr + tid), x1 = __ldg(xr + tid + 256), x2 = __ldg(xr + tid + 512);

        float p[HH];
#pragma unroll
        for (int h = 0; h < HH; h++)
            p[h] = fmaf(x0, ur[h * 3 + 0], fmaf(x1, ur[h * 3 + 1], x2 * ur[h * 3 + 2]));

#pragma unroll
        for (int h = 0; h < HH; h++) {
            float v = p[h];
            v += __shfl_down_sync(FULLM, v, 16);
            v += __shfl_down_sync(FULLM, v, 8);
            v += __shfl_down_sync(FULLM, v, 4);
            v += __shfl_down_sync(FULLM, v, 2);
            v += __shfl_down_sync(FULLM, v, 1);
            p[h] = v;
        }
        if (lane == 0) {
#pragma unroll
            for (int h = 0; h < HH; h++) red[h * 8 + warp] = p[h];
        }
        __syncthreads();
        if (tid < HH) {
            float s = bet[tid];
#pragma unroll
            for (int w = 0; w < 8; w++) s += red[tid * 8 + w];
            g_dots[(size_t)(b * HH + tid) * N + j] = SCALE * s;
        }
        __syncthreads();
    }
}

// ---------------- K4: softmax over j per (b,h), mean over h -----------------
// grid 32, block 256. Writes class_attention directly to d_out.
__global__ void k_softmax(float* __restrict__ out) {
    int b = blockIdx.x, tid = threadIdx.x;
    int lane = tid & 31, warp = tid >> 5;
    __shared__ float ca[NK];
    __shared__ float red[8];
    for (int i = tid; i < NK; i += 256) ca[i] = 0.f;
    __syncthreads();

    for (int h = 0; h < HH; h++) {
        const float* dp = &g_dots[(size_t)(b * HH + h) * N];
        float d0 = dp[tid];
        float d1 = dp[tid + 256];                     // tid+256 <= 511 < 577 always
        float d2 = (tid + 512 < N) ? dp[tid + 512] : -1e30f;

        // block max
        float m = fmaxf(d0, fmaxf(d1, d2));
        for (int o = 16; o; o >>= 1) m = fmaxf(m, __shfl_xor_sync(FULLM, m, o));
        if (lane == 0) red[warp] = m;
        __syncthreads();
        if (tid < 32) {
            float v = (tid < 8) ? red[tid] : -1e30f;
            for (int o = 4; o; o >>= 1) v = fmaxf(v, __shfl_xor_sync(FULLM, v, o));
            if (tid == 0) red[0] = v;
        }
        __syncthreads();
        m = red[0];
        __syncthreads();

        float e0 = __expf(d0 - m);
        float e1 = __expf(d1 - m);
        float e2 = (tid + 512 < N) ? __expf(d2 - m) : 0.f;

        float s = e0 + e1 + e2;
        for (int o = 16; o; o >>= 1) s += __shfl_xor_sync(FULLM, s, o);
        if (lane == 0) red[warp] = s;
        __syncthreads();
        if (tid < 32) {
            float v = (tid < 8) ? red[tid] : 0.f;
            for (int o = 4; o; o >>= 1) v += __shfl_xor_sync(FULLM, v, o);
            if (tid == 0) red[0] = v;
        }
        __syncthreads();
        float inv = 1.f / red[0];
        __syncthreads();

        if (tid >= 1)        ca[tid - 1]   += e0 * inv;   // j = tid (skip j=0)
        ca[tid + 255] += e1 * inv;                        // j = tid+256
        if (tid + 512 < N)   ca[tid + 511] += e2 * inv;   // j = tid+512
        __syncthreads();
    }
    const float invH = 1.f / (float)HH;
    for (int i = tid; i < NK; i += 256)
        out[OFF_CA + (size_t)b * NK + i] = ca[i] * invH;
}

// ---------------- K5: exact top-k + ascending-index compaction --------------
// grid 32, block 576. Matches jax.lax.top_k tie-break (value desc, index asc).
__global__ void k_topk(float* __restrict__ out, const float* __restrict__ keep_rate) {
    int b = blockIdx.x, i = threadIdx.x;
    __shared__ float vals[NK];
    __shared__ int sel[NK];
    vals[i] = out[OFF_CA + (size_t)b * NK + i];
    __syncthreads();

    int K = (int)ceilf(keep_rate[0] * (float)NK);   // = 404
    float vi = vals[i];
    int rank = 0;
    for (int j = 0; j < NK; j++) {
        float vj = vals[j];
        rank += (vj > vi) || (vj == vi && j < i);
    }
    sel[i] = (rank < K) ? 1 : 0;
    __syncthreads();
    if (sel[i]) {
        int pos = 0;
        for (int j = 0; j < i; j++) pos += sel[j];
        out[OFF_IND + (size_t)b * FT + pos] = (float)i;
        g_ind[b * FT + pos] = i;
    }
    if (b == 0 && i == 0) out[OFF_FT] = (float)K;
}

// ---------------- K6: index = broadcast(ind) over channel dim ---------------
__global__ void k_index(float* __restrict__ out) {
    long long idx = (long long)blockIdx.x * 256 + threadIdx.x;
    const long long TOT = (long long)B * FT * C;
    if (idx >= TOT) return;
    int b = (int)(idx / ((long long)FT * C));
    int t = (int)((idx / C) % FT);
    out[OFF_INDEX + idx] = (float)g_ind[b * FT + t];
}

// ---------------- launch -----------------------------------------------------
extern "C" void kernel_launch(void* const* d_in, const int* in_sizes, int n_in,
                              void* d_out, int out_size) {
    const float* x    = (const float*)d_in[0];
    const float* kr   = (const float*)d_in[1];
    const float* Wqkv = (const float*)d_in[2];
    const float* bqkv = (const float*)d_in[3];
    float* out = (float*)d_out;

    // output[0] is x unchanged
    cudaMemcpyAsync(out + OFF_X, x, (size_t)B * N * C * sizeof(float),
                    cudaMemcpyDeviceToDevice, 0);

    k_qproj<<<B, C>>>(x, Wqkv, bqkv);
    k_uproj<<<96, 384>>>(Wqkv, bqkv);
    k_dots<<<dim3(B, 16), 256>>>(x);
    k_softmax<<<B, 256>>>(out);
    k_topk<<<B, NK>>>(out, kr);
    k_index<<<(unsigned)(((long long)B * FT * C + 255) / 256), 256>>>(out);
}

// round 4
// speedup vs baseline: 1.7283x; 1.7283x over previous
#include <cuda_runtime.h>
#include <cstdint>

// Problem constants (ViT-B/16 @384: b=32, n=577, c=768, H=12, d=64, keep=0.7)
#define B   32
#define N   577
#define C   768
#define HH  12
#define DD  64
#define NK  576          // n-1 patch tokens
#define FT  404          // ceil(0.7*576)
#define SCALE 0.125f     // (c/H)^-0.5 = 64^-0.5

// Output layout (tuple leaves flattened, concatenated, float32):
//  x [32,577,768] | index [32,404,768] | ind [32,404] | class_attention [32,576] | final_tokens [1]
#define OFF_X      0ll
#define OFF_INDEX  14180352ll
#define OFF_IND    24109056ll
#define OFF_CA     24121984ll
#define OFF_FT     24140416ll

#define FULLM 0xFFFFFFFFu

// ---------------- scratch (device globals; no allocation allowed) ------------
__device__ float g_qp[6][B * C];           // qproj partials (split-K over cc)
__device__ float g_q[B * C];               // q for CLS token, [b, h*64+d]
__device__ float g_u[B * HH * C];          // folded key-projection vectors [b,h,c]
__device__ float g_beta[B * HH];           // bias dot terms
__device__ float g_dots[B * HH * N];       // CLS attention logits
__device__ float g_probs[B * HH * NK];     // per-head softmax probs over patch tokens
__device__ int   g_ind[B * FT];            // selected indices (sorted by construction)

// ---------------- K1a: qproj partials. grid (32,6), block 768 ---------------
// partial[s][b][col] = sum_{cc in slice s} x[b,0,cc] * Wq[cc,col]
__global__ void __launch_bounds__(768) k_qprojp(const float* __restrict__ x,
                                                const float* __restrict__ W) {
    int b = blockIdx.x, s = blockIdx.y, col = threadIdx.x;
    __shared__ float xs[128];
    if (col < 128) xs[col] = x[(size_t)b * N * C + s * 128 + col];
    __syncthreads();
    float acc = 0.f;
#pragma unroll 8
    for (int i = 0; i < 128; i++)
        acc = fmaf(xs[i], W[(size_t)(s * 128 + i) * 3 * C + col], acc);
    g_qp[s][b * C + col] = acc;
}

// ---------------- K1b: q = sum partials + bias. grid 32, block 768 ----------
__global__ void k_qreduce(const float* __restrict__ bq) {
    int b = blockIdx.x, col = threadIdx.x;
    float acc = bq[col];
#pragma unroll
    for (int s = 0; s < 6; s++) acc += g_qp[s][b * C + col];
    g_q[b * C + col] = acc;
}

// ---------------- K2: u[b,h,c] = sum_d Wk[c,h*64+d]*q[b,h,d]; beta ----------
// grid 192 blocks (4 cc each), block 384 threads (= 32 b * 12 h)
__global__ void k_uproj(const float* __restrict__ W,
                        const float* __restrict__ bqkv) {
    int cc0 = blockIdx.x * 4;
    int tid = threadIdx.x;
    int b = tid / HH, h = tid % HH;

    float q[DD];
    const float4* qp = (const float4*)&g_q[b * C + h * DD];
#pragma unroll
    for (int i = 0; i < DD / 4; i++) {
        float4 v = qp[i];
        q[4 * i + 0] = v.x; q[4 * i + 1] = v.y; q[4 * i + 2] = v.z; q[4 * i + 3] = v.w;
    }

    __shared__ float w[4][C];
    // stage 4 Wk rows (cols 768..1535) cooperatively
#pragma unroll
    for (int s = 0; s < 4; s++) {
        w[s][tid]       = W[(size_t)(cc0 + s) * 3 * C + C + tid];
        w[s][tid + 384] = W[(size_t)(cc0 + s) * 3 * C + C + tid + 384];
    }
    __syncthreads();
#pragma unroll
    for (int s = 0; s < 4; s++) {
        float acc = 0.f;
#pragma unroll
        for (int d = 0; d < DD; d++) acc = fmaf(w[s][h * DD + d], q[d], acc);
        g_u[(size_t)(b * HH + h) * C + cc0 + s] = acc;
    }
    if (blockIdx.x == 0) {
        float acc = 0.f;
#pragma unroll
        for (int d = 0; d < DD; d++) acc = fmaf(bqkv[C + h * DD + d], q[d], acc);
        g_beta[tid] = acc;   // tid == b*12+h
    }
}

// ---------------- K3: dots[b,h,j] = scale*(x[b,j,:]·u[b,h,:] + beta) --------
// grid (32, 37) — 16 j per block; block 256. u in registers, j-prefetch pipeline.
#define JPB 16
__global__ void __launch_bounds__(256) k_dots(const float* __restrict__ x) {
    int b = blockIdx.x, tid = threadIdx.x;
    int lane = tid & 31, warp = tid >> 5;

    float ur[HH * 3];
#pragma unroll
    for (int h = 0; h < HH; h++)
#pragma unroll
        for (int s = 0; s < 3; s++)
            ur[h * 3 + s] = g_u[(size_t)(b * HH + h) * C + s * 256 + tid];

    __shared__ float bet[HH];
    __shared__ float red[HH * 8];
    if (tid < HH) bet[tid] = g_beta[b * HH + tid];
    __syncthreads();

    int j0 = blockIdx.y * JPB;
    if (j0 >= N) return;

    const float* xr = x + ((size_t)b * N + j0) * C;
    float x0 = __ldg(xr + tid), x1 = __ldg(xr + tid + 256), x2 = __ldg(xr + tid + 512);

    for (int jj = 0; jj < JPB; jj++) {
        int j = j0 + jj;
        if (j >= N) break;
        // prefetch next row while reducing this one
        float n0 = 0.f, n1 = 0.f, n2 = 0.f;
        if (jj + 1 < JPB && j + 1 < N) {
            const float* xn = x + ((size_t)b * N + j + 1) * C;
            n0 = __ldg(xn + tid); n1 = __ldg(xn + tid + 256); n2 = __ldg(xn + tid + 512);
        }

        float p[HH];
#pragma unroll
        for (int h = 0; h < HH; h++)
            p[h] = fmaf(x0, ur[h * 3 + 0], fmaf(x1, ur[h * 3 + 1], x2 * ur[h * 3 + 2]));

#pragma unroll
        for (int h = 0; h < HH; h++) {
            float v = p[h];
            v += __shfl_down_sync(FULLM, v, 16);
            v += __shfl_down_sync(FULLM, v, 8);
            v += __shfl_down_sync(FULLM, v, 4);
            v += __shfl_down_sync(FULLM, v, 2);
            v += __shfl_down_sync(FULLM, v, 1);
            p[h] = v;
        }
        if (lane == 0) {
#pragma unroll
            for (int h = 0; h < HH; h++) red[h * 8 + warp] = p[h];
        }
        __syncthreads();
        if (tid < HH) {
            float s = bet[tid];
#pragma unroll
            for (int w = 0; w < 8; w++) s += red[tid * 8 + w];
            g_dots[(size_t)(b * HH + tid) * N + j] = SCALE * s;
        }
        __syncthreads();
        x0 = n0; x1 = n1; x2 = n2;
    }
}

// ---------------- K4: softmax per (b,h). grid (32,12), block 256 ------------
__global__ void k_softmax() {
    int b = blockIdx.x, h = blockIdx.y, tid = threadIdx.x;
    int lane = tid & 31, warp = tid >> 5;
    __shared__ float red[8];

    const float* dp = &g_dots[(size_t)(b * HH + h) * N];
    float d0 = dp[tid];
    float d1 = dp[tid + 256];
    float d2 = (tid + 512 < N) ? dp[tid + 512] : -1e30f;

    float m = fmaxf(d0, fmaxf(d1, d2));
    for (int o = 16; o; o >>= 1) m = fmaxf(m, __shfl_xor_sync(FULLM, m, o));
    if (lane == 0) red[warp] = m;
    __syncthreads();
    if (tid < 32) {
        float v = (tid < 8) ? red[tid] : -1e30f;
        for (int o = 4; o; o >>= 1) v = fmaxf(v, __shfl_xor_sync(FULLM, v, o));
        if (tid == 0) red[0] = v;
    }
    __syncthreads();
    m = red[0];
    __syncthreads();

    float e0 = __expf(d0 - m);
    float e1 = __expf(d1 - m);
    float e2 = (tid + 512 < N) ? __expf(d2 - m) : 0.f;

    float s = e0 + e1 + e2;
    for (int o = 16; o; o >>= 1) s += __shfl_xor_sync(FULLM, s, o);
    if (lane == 0) red[warp] = s;
    __syncthreads();
    if (tid < 32) {
        float v = (tid < 8) ? red[tid] : 0.f;
        for (int o = 4; o; o >>= 1) v += __shfl_xor_sync(FULLM, v, o);
        if (tid == 0) red[0] = v;
    }
    __syncthreads();
    float inv = 1.f / red[0];

    float* pp = &g_probs[(size_t)(b * HH + h) * NK];
    if (tid >= 1)      pp[tid - 1]   = e0 * inv;   // j = tid (skip j=0)
    pp[tid + 255] = e1 * inv;                      // j = tid+256
    if (tid + 512 < N) pp[tid + 511] = e2 * inv;   // j = tid+512
}

// ---------------- K5: head-mean + exact top-k + compaction ------------------
// grid 32, block 576 (18 full warps). jax.lax.top_k tie-break: value desc, idx asc.
__global__ void k_topk(float* __restrict__ out, const float* __restrict__ keep_rate) {
    int b = blockIdx.x, i = threadIdx.x;
    int lane = i & 31, warp = i >> 5;
    __shared__ float vals[NK];
    __shared__ int wcnt[18];

    float s = 0.f;
#pragma unroll
    for (int h = 0; h < HH; h++) s += g_probs[(size_t)(b * HH + h) * NK + i];
    float vi = s * (1.f / (float)HH);
    vals[i] = vi;
    out[OFF_CA + (size_t)b * NK + i] = vi;
    __syncthreads();

    int K = (int)ceilf(keep_rate[0] * (float)NK);   // = 404
    int rank = 0;
#pragma unroll 8
    for (int j = 0; j < NK; j++) {
        float vj = vals[j];
        rank += (vj > vi) || (vj == vi && j < i);
    }
    bool sel = (rank < K);

    unsigned m = __ballot_sync(FULLM, sel);
    if (lane == 0) wcnt[warp] = __popc(m);
    __syncthreads();
    int base = 0;
    for (int w = 0; w < warp; w++) base += wcnt[w];
    int pos = base + __popc(m & ((1u << lane) - 1u));

    if (sel) {
        out[OFF_IND + (size_t)b * FT + pos] = (float)i;
        g_ind[b * FT + pos] = i;
    }
    if (b == 0 && i == 0) out[OFF_FT] = (float)K;
}

// ---------------- K6: index broadcast, no divisions -------------------------
// grid (3, B*FT), block 256: row = blockIdx.y, 768 cols split across 3 blocks.
__global__ void k_index(float* __restrict__ out) {
    int row = blockIdx.y;
    float v = (float)g_ind[row];
    out[OFF_INDEX + (size_t)row * C + blockIdx.x * 256 + threadIdx.x] = v;
}

// ---------------- launch -----------------------------------------------------
extern "C" void kernel_launch(void* const* d_in, const int* in_sizes, int n_in,
                              void* d_out, int out_size) {
    const float* x    = (const float*)d_in[0];
    const float* kr   = (const float*)d_in[1];
    const float* Wqkv = (const float*)d_in[2];
    const float* bqkv = (const float*)d_in[3];
    float* out = (float*)d_out;

    // output[0] is x unchanged
    cudaMemcpyAsync(out + OFF_X, x, (size_t)B * N * C * sizeof(float),
                    cudaMemcpyDeviceToDevice, 0);

    k_qprojp<<<dim3(B, 6), C>>>(x, Wqkv);
    k_qreduce<<<B, C>>>(bqkv);
    k_uproj<<<192, 384>>>(Wqkv, bqkv);
    k_dots<<<dim3(B, 37), 256>>>(x);
    k_softmax<<<dim3(B, HH), 256>>>();
    k_topk<<<B, NK>>>(out, kr);
    k_index<<<dim3(3, B * FT), 256>>>(out);
}

// round 5
// speedup vs baseline: 2.0243x; 1.1712x over previous
#include <cuda_runtime.h>
#include <cstdint>

// Problem constants (ViT-B/16 @384: b=32, n=577, c=768, H=12, d=64, keep=0.7)
#define B   32
#define N   577
#define C   768
#define HH  12
#define DD  64
#define NK  576          // n-1 patch tokens
#define FT  404          // ceil(0.7*576)
#define SCALE 0.125f     // (c/H)^-0.5

// Output layout (tuple leaves flattened, concatenated, float32):
//  x [32,577,768] | index [32,404,768] | ind [32,404] | class_attention [32,576] | final_tokens [1]
#define OFF_X      0ll
#define OFF_INDEX  14180352ll
#define OFF_IND    24109056ll
#define OFF_CA     24121984ll
#define OFF_FT     24140416ll

#define FULLM 0xFFFFFFFFu

// k_dots tiling
#define CS   12          // c-slices (blocks in y)
#define CSL  64          // c per slice
#define CT   16          // c per smem stage tile
#define JT   640         // padded j extent (5*128)
#define JPAD 643         // smem row pad (bank spread)

// ---------------- scratch (device globals; no allocation allowed) ------------
__device__ float g_qp[6][B * C];            // qproj partials
__device__ float g_q[B * C];                // CLS q, [b, h*64+d]
__device__ float g_u[B * HH * C];           // folded key vectors [b,h,c]
__device__ float g_beta[B * HH];            // bias dot terms
__device__ float g_dotsp[CS * B * HH * JT]; // c-slice partial logits
__device__ float g_probs[B * HH * NK];      // per-head softmax probs
__device__ int   g_ind[B * FT];             // selected indices

// ---------------- K1a: qproj partials. grid (32,6), block 768 ---------------
__global__ void __launch_bounds__(768) k_qprojp(const float* __restrict__ x,
                                                const float* __restrict__ W) {
    int b = blockIdx.x, s = blockIdx.y, col = threadIdx.x;
    __shared__ float xs[128];
    if (col < 128) xs[col] = x[(size_t)b * N * C + s * 128 + col];
    __syncthreads();
    float acc = 0.f;
#pragma unroll 8
    for (int i = 0; i < 128; i++)
        acc = fmaf(xs[i], W[(size_t)(s * 128 + i) * 3 * C + col], acc);
    g_qp[s][b * C + col] = acc;
}

// ---------------- K1b: q = sum partials + bias. grid 32, block 768 ----------
__global__ void k_qreduce(const float* __restrict__ bq) {
    int b = blockIdx.x, col = threadIdx.x;
    float acc = bq[col];
#pragma unroll
    for (int s = 0; s < 6; s++) acc += g_qp[s][b * C + col];
    g_q[b * C + col] = acc;
}

// ---------------- K2: u[b,h,c] = sum_d Wk[c,h*64+d]*q[b,h,d]; beta ----------
// grid 192 blocks (4 cc each), block 384 threads (= 32 b * 12 h)
__global__ void k_uproj(const float* __restrict__ W,
                        const float* __restrict__ bqkv) {
    int cc0 = blockIdx.x * 4;
    int tid = threadIdx.x;
    int b = tid / HH, h = tid % HH;

    float q[DD];
    const float4* qp = (const float4*)&g_q[b * C + h * DD];
#pragma unroll
    for (int i = 0; i < DD / 4; i++) {
        float4 v = qp[i];
        q[4 * i + 0] = v.x; q[4 * i + 1] = v.y; q[4 * i + 2] = v.z; q[4 * i + 3] = v.w;
    }

    __shared__ float w[4][C];
#pragma unroll
    for (int s = 0; s < 4; s++) {
        w[s][tid]       = W[(size_t)(cc0 + s) * 3 * C + C + tid];
        w[s][tid + 384] = W[(size_t)(cc0 + s) * 3 * C + C + tid + 384];
    }
    __syncthreads();
#pragma unroll
    for (int s = 0; s < 4; s++) {
        float acc = 0.f;
#pragma unroll
        for (int d = 0; d < DD; d++) acc = fmaf(w[s][h * DD + d], q[d], acc);
        g_u[(size_t)(b * HH + h) * C + cc0 + s] = acc;
    }
    if (blockIdx.x == 0) {
        float acc = 0.f;
#pragma unroll
        for (int d = 0; d < DD; d++) acc = fmaf(bqkv[C + h * DD + d], q[d], acc);
        g_beta[tid] = acc;   // tid == b*12+h
    }
}

// ---------------- K3: dots partials, register-blocked GEMM ------------------
// grid (B, CS); block 128. Thread owns 5 j (t+128q) x 12 h accumulators.
// Also performs the x -> out copy for its (all j, c-slice) panel.
__global__ void __launch_bounds__(128) k_dots(const float* __restrict__ x,
                                              float* __restrict__ out) {
    int b = blockIdx.x, cs = blockIdx.y, t = threadIdx.x;
    int c0 = cs * CSL;

    __shared__ float xsT[CT][JPAD];    // transposed x tile: [c][j]
    __shared__ float usT[CSL][12];     // transposed u slice: [c][h] (48B rows, 16B-aligned)

    // stage u^T for this c-slice (once)
    for (int i = t; i < HH * CSL; i += 128) {
        int h = i / CSL, cc = i % CSL;
        usT[cc][h] = g_u[((size_t)b * HH + h) * C + c0 + cc];
    }

    float acc[5][12];
#pragma unroll
    for (int q = 0; q < 5; q++)
#pragma unroll
        for (int h = 0; h < 12; h++) acc[q][h] = 0.f;

    for (int tile = 0; tile < CSL / CT; tile++) {
        int ct = tile * CT;
        __syncthreads();   // prev compute done before restage (also covers usT)
        // stage x^T tile [CT c x JT j]; fused x->out copy
        for (int f = t; f < (JT * CT) / 4; f += 128) {
            int jr = f >> 2, fc = f & 3;          // jr: row, fc: float4 within 16-c tile
            float4 v = make_float4(0.f, 0.f, 0.f, 0.f);
            if (jr < N) {
                size_t g = ((size_t)b * N + jr) * C + c0 + ct + fc * 4;
                v = *(const float4*)&x[g];
                *(float4*)&out[OFF_X + g] = v;    // fused copy of x
            }
            int cc = fc * 4;
            xsT[cc + 0][jr] = v.x; xsT[cc + 1][jr] = v.y;
            xsT[cc + 2][jr] = v.z; xsT[cc + 3][jr] = v.w;
        }
        __syncthreads();
#pragma unroll 4
        for (int cc = 0; cc < CT; cc++) {
            const float4 u0 = *(const float4*)&usT[ct + cc][0];
            const float4 u1 = *(const float4*)&usT[ct + cc][4];
            const float4 u2 = *(const float4*)&usT[ct + cc][8];
#pragma unroll
            for (int q = 0; q < 5; q++) {
                float xv = xsT[cc][t + 128 * q];
                acc[q][0]  = fmaf(xv, u0.x, acc[q][0]);
                acc[q][1]  = fmaf(xv, u0.y, acc[q][1]);
                acc[q][2]  = fmaf(xv, u0.z, acc[q][2]);
                acc[q][3]  = fmaf(xv, u0.w, acc[q][3]);
                acc[q][4]  = fmaf(xv, u1.x, acc[q][4]);
                acc[q][5]  = fmaf(xv, u1.y, acc[q][5]);
                acc[q][6]  = fmaf(xv, u1.z, acc[q][6]);
                acc[q][7]  = fmaf(xv, u1.w, acc[q][7]);
                acc[q][8]  = fmaf(xv, u2.x, acc[q][8]);
                acc[q][9]  = fmaf(xv, u2.y, acc[q][9]);
                acc[q][10] = fmaf(xv, u2.z, acc[q][10]);
                acc[q][11] = fmaf(xv, u2.w, acc[q][11]);
            }
        }
    }

    // write partial logits (coalesced in j)
#pragma unroll
    for (int q = 0; q < 5; q++) {
        int j = t + 128 * q;
        if (j < N) {
#pragma unroll
            for (int h = 0; h < 12; h++)
                g_dotsp[((size_t)(cs * B + b) * HH + h) * JT + j] = acc[q][h];
        }
    }
}

// ---------------- K4: sum partials + scale + beta + softmax per (b,h) -------
// grid (32,12), block 256. Writes per-head probs to g_probs.
__global__ void k_softmax() {
    int b = blockIdx.x, h = blockIdx.y, tid = threadIdx.x;
    int lane = tid & 31, warp = tid >> 5;
    __shared__ float red[8];

    float beta = g_beta[b * HH + h];
    float d[3];
#pragma unroll
    for (int r = 0; r < 3; r++) {
        int j = tid + 256 * r;
        float s = beta;
        if (j < N) {
#pragma unroll
            for (int cs = 0; cs < CS; cs++)
                s += g_dotsp[((size_t)(cs * B + b) * HH + h) * JT + j];
            d[r] = SCALE * s;
        } else d[r] = -1e30f;
    }

    float m = fmaxf(d[0], fmaxf(d[1], d[2]));
    for (int o = 16; o; o >>= 1) m = fmaxf(m, __shfl_xor_sync(FULLM, m, o));
    if (lane == 0) red[warp] = m;
    __syncthreads();
    if (tid < 32) {
        float v = (tid < 8) ? red[tid] : -1e30f;
        for (int o = 4; o; o >>= 1) v = fmaxf(v, __shfl_xor_sync(FULLM, v, o));
        if (tid == 0) red[0] = v;
    }
    __syncthreads();
    m = red[0];
    __syncthreads();

    float e0 = __expf(d[0] - m);
    float e1 = __expf(d[1] - m);
    float e2 = (tid + 512 < N) ? __expf(d[2] - m) : 0.f;

    float s = e0 + e1 + e2;
    for (int o = 16; o; o >>= 1) s += __shfl_xor_sync(FULLM, s, o);
    if (lane == 0) red[warp] = s;
    __syncthreads();
    if (tid < 32) {
        float v = (tid < 8) ? red[tid] : 0.f;
        for (int o = 4; o; o >>= 1) v += __shfl_xor_sync(FULLM, v, o);
        if (tid == 0) red[0] = v;
    }
    __syncthreads();
    float inv = 1.f / red[0];

    float* pp = &g_probs[(size_t)(b * HH + h) * NK];
    if (tid >= 1)      pp[tid - 1]   = e0 * inv;   // j = tid (skip CLS)
    pp[tid + 255] = e1 * inv;                      // j = tid+256
    if (tid + 512 < N) pp[tid + 511] = e2 * inv;   // j = tid+512
}

// ---------------- K5: head-mean + exact top-k + compaction ------------------
// grid 32, block 576. jax.lax.top_k tie-break: value desc, index asc.
__global__ void k_topk(float* __restrict__ out, const float* __restrict__ keep_rate) {
    int b = blockIdx.x, i = threadIdx.x;
    int lane = i & 31, warp = i >> 5;
    __shared__ float4 vals4[NK / 4];
    __shared__ int wcnt[18];
    float* vals = (float*)vals4;

    float s = 0.f;
#pragma unroll
    for (int h = 0; h < HH; h++) s += g_probs[(size_t)(b * HH + h) * NK + i];
    float vi = s * (1.f / (float)HH);
    vals[i] = vi;
    out[OFF_CA + (size_t)b * NK + i] = vi;
    __syncthreads();

    int K = (int)ceilf(keep_rate[0] * (float)NK);   // 404
    int rank = 0;
#pragma unroll 4
    for (int jq = 0; jq < NK / 4; jq++) {
        float4 v = vals4[jq];
        int j = jq * 4;
        rank += (v.x > vi) || (v.x == vi && (j + 0) < i);
        rank += (v.y > vi) || (v.y == vi && (j + 1) < i);
        rank += (v.z > vi) || (v.z == vi && (j + 2) < i);
        rank += (v.w > vi) || (v.w == vi && (j + 3) < i);
    }
    bool sel = (rank < K);

    unsigned m = __ballot_sync(FULLM, sel);
    if (lane == 0) wcnt[warp] = __popc(m);
    __syncthreads();
    int base = 0;
    for (int w = 0; w < warp; w++) base += wcnt[w];
    int pos = base + __popc(m & ((1u << lane) - 1u));

    if (sel) {
        out[OFF_IND + (size_t)b * FT + pos] = (float)i;
        g_ind[b * FT + pos] = i;
    }
    if (b == 0 && i == 0) out[OFF_FT] = (float)K;
}

// ---------------- K6: index broadcast, float4 stores ------------------------
// grid B*FT blocks (one row each), block 192 (= 768/4 float4 per row)
__global__ void k_index(float* __restrict__ out) {
    int row = blockIdx.x;
    float v = (float)g_ind[row];
    float4* o = (float4*)(out + OFF_INDEX + (size_t)row * C);
    o[threadIdx.x] = make_float4(v, v, v, v);
}

// ---------------- launch -----------------------------------------------------
extern "C" void kernel_launch(void* const* d_in, const int* in_sizes, int n_in,
                              void* d_out, int out_size) {
    const float* x    = (const float*)d_in[0];
    const float* kr   = (const float*)d_in[1];
    const float* Wqkv = (const float*)d_in[2];
    const float* bqkv = (const float*)d_in[3];
    float* out = (float*)d_out;

    k_qprojp<<<dim3(B, 6), C>>>(x, Wqkv);
    k_qreduce<<<B, C>>>(bqkv);
    k_uproj<<<192, 384>>>(Wqkv, bqkv);
    k_dots<<<dim3(B, CS), 128>>>(x, out);     // also copies x -> out
    k_softmax<<<dim3(B, HH), 256>>>();
    k_topk<<<B, NK>>>(out, kr);
    k_index<<<B * FT, C / 4>>>(out);
}